// round 1
// baseline (speedup 1.0000x reference)
#include <cuda_runtime.h>
#include <math.h>

#define BM 16
#define BK 256
#define NTHREADS 256
#define NEGV -1e9f

// ---------------------------------------------------------------------------
// Mask dtype handling: the reference produces jax bool arrays; the harness may
// hand them to us as int32, uint8, or float32. Detect at runtime (deterministic,
// reads only the first 256 bytes which every candidate layout owns).
// mode: 0 = int32, 1 = byte, 2 = float32
// ---------------------------------------------------------------------------
__device__ __forceinline__ bool mask_at(const void* m, int mode, long long idx) {
    if (mode == 1) return ((const unsigned char*)m)[idx] != 0;
    if (mode == 2) return ((const float*)m)[idx] != 0.0f;
    return ((const int*)m)[idx] != 0;
}

__device__ int detect_mode(const void* p) {
    const unsigned int* w = (const unsigned int*)p;
    bool i32 = true, f32 = true;
    #pragma unroll 4
    for (int i = 0; i < 64; i++) {
        unsigned int v = w[i];
        if (v != 0u && v != 1u) i32 = false;
        if (v != 0u && v != 0x3F800000u) f32 = false;
    }
    if (i32) return 0;
    if (f32) return 2;
    return 1;
}

// ---------------------------------------------------------------------------
// Fused attention kernel. One CTA = (batch n, 16 query rows).
// Phase 1: load Q tile (scaled by 1/sqrt(64)) into smem
// Phase 2: S = Q K^T + masks, full 16 x M score strip kept in smem
// Phase 3: row softmax in smem, normalized weights written once to gmem
// Phase 4: out = P V with per-thread partial sums over key sub-chunks,
//          reduced through smem.
// D is fixed at 64 for this problem.
// ---------------------------------------------------------------------------
extern "C" __global__ void __launch_bounds__(NTHREADS, 1)
sdpa_kernel(const float* __restrict__ Q, const float* __restrict__ K,
            const float* __restrict__ V, const void* __restrict__ kpm,
            const void* __restrict__ am, float* __restrict__ outp,
            float* __restrict__ attnp, int N, int M)
{
    extern __shared__ float smdyn[];
    float* Qs = smdyn;                 // BM * 68  (padded rows, float4-aligned)
    float* Ks = smdyn + BM * 68;       // BK * 68  (K tile, later reused for V)
    float* S  = Ks + BK * 68;          // BM * M   (score strip)
    __shared__ int modes[2];

    const int tid = threadIdx.x;
    const int n   = blockIdx.y;
    const int m0  = blockIdx.x * BM;
    const long long rowBase = (long long)n * M;   // row index base for Q/K/V/kpm

    if (tid == 0)  modes[0] = detect_mode(kpm);
    if (tid == 32) modes[1] = detect_mode(am);

    // ---- Phase 1: Q tile (pre-scaled) ----
    for (int i = tid; i < BM * 16; i += NTHREADS) {
        int r = i >> 4, d4 = i & 15;
        float4 v = ((const float4*)(Q + (rowBase + m0 + r) * 64))[d4];
        v.x *= 0.125f; v.y *= 0.125f; v.z *= 0.125f; v.w *= 0.125f;
        *(float4*)(Qs + r * 68 + d4 * 4) = v;
    }
    __syncthreads();
    const int kpmMode = modes[0];
    const int amMode  = modes[1];

    // ---- Phase 2: scores ----
    // thread tile: 8 rows x 2 keys (keys kg and kg+128 within the BK tile,
    // stride-1 kg across a warp => conflict-free LDS.128 on the K tile)
    const int rg = tid >> 7;     // 0..1
    const int kg = tid & 127;    // 0..127
    const int r0 = rg * 8;

    for (int kt = 0; kt < M; kt += BK) {
        for (int i = tid; i < BK * 16; i += NTHREADS) {
            int r = i >> 4, d4 = i & 15;
            float4 v = ((const float4*)(K + (rowBase + kt + r) * 64))[d4];
            *(float4*)(Ks + r * 68 + d4 * 4) = v;
        }
        __syncthreads();

        float acc0[8], acc1[8];
        #pragma unroll
        for (int i = 0; i < 8; i++) { acc0[i] = 0.f; acc1[i] = 0.f; }

        #pragma unroll
        for (int d4 = 0; d4 < 16; d4++) {
            float4 k0 = *(const float4*)(Ks + kg * 68 + d4 * 4);
            float4 k1 = *(const float4*)(Ks + (kg + 128) * 68 + d4 * 4);
            #pragma unroll
            for (int i = 0; i < 8; i++) {
                float4 q = *(const float4*)(Qs + (r0 + i) * 68 + d4 * 4);
                acc0[i] = fmaf(q.x, k0.x, fmaf(q.y, k0.y, fmaf(q.z, k0.z, fmaf(q.w, k0.w, acc0[i]))));
                acc1[i] = fmaf(q.x, k1.x, fmaf(q.y, k1.y, fmaf(q.z, k1.z, fmaf(q.w, k1.w, acc1[i]))));
            }
        }

        float kp0 = mask_at(kpm, kpmMode, rowBase + kt + kg)       ? NEGV : 0.f;
        float kp1 = mask_at(kpm, kpmMode, rowBase + kt + kg + 128) ? NEGV : 0.f;
        #pragma unroll
        for (int i = 0; i < 8; i++) {
            long long arow = (long long)(m0 + r0 + i) * M + kt;
            float a0 = mask_at(am, amMode, arow + kg)       ? NEGV : 0.f;
            float a1 = mask_at(am, amMode, arow + kg + 128) ? NEGV : 0.f;
            S[(r0 + i) * M + kt + kg]       = acc0[i] + kp0 + a0;
            S[(r0 + i) * M + kt + kg + 128] = acc1[i] + kp1 + a1;
        }
        __syncthreads();
    }

    // ---- Phase 3: row softmax (8 warps x 2 rows each), write attn weights ----
    const int warp = tid >> 5, lane = tid & 31;
    #pragma unroll
    for (int rr = 0; rr < 2; rr++) {
        int r = warp * 2 + rr;
        float* Srow = S + r * M;

        float mx = -3.0e38f;
        for (int c = lane; c < M; c += 32) mx = fmaxf(mx, Srow[c]);
        #pragma unroll
        for (int o = 16; o; o >>= 1) mx = fmaxf(mx, __shfl_xor_sync(0xffffffffu, mx, o));

        float sum = 0.f;
        for (int c = lane; c < M; c += 32) {
            float e = __expf(Srow[c] - mx);
            Srow[c] = e;
            sum += e;
        }
        #pragma unroll
        for (int o = 16; o; o >>= 1) sum += __shfl_xor_sync(0xffffffffu, sum, o);

        float inv = 1.f / sum;
        long long gbase = (rowBase + m0 + r) * (long long)M;
        for (int c = lane; c < M; c += 32) {
            float p = Srow[c] * inv;
            Srow[c] = p;
            if (attnp) attnp[gbase + c] = p;
        }
    }
    __syncthreads();

    // ---- Phase 4: out = P @ V ----
    // thread slot: (c8 = key sub-chunk 0..7, rg2 = row half 0..1, dg = d-group 0..15)
    const int dg  = tid & 15;
    const int rg2 = (tid >> 4) & 1;
    const int c8  = tid >> 5;
    float4 acc[8];
    #pragma unroll
    for (int i = 0; i < 8; i++) acc[i] = make_float4(0.f, 0.f, 0.f, 0.f);

    for (int vt = 0; vt < M; vt += BK) {
        for (int i = tid; i < BK * 16; i += NTHREADS) {
            int r = i >> 4, d4 = i & 15;
            float4 v = ((const float4*)(V + (rowBase + vt + r) * 64))[d4];
            *(float4*)(Ks + r * 68 + d4 * 4) = v;
        }
        __syncthreads();

        const int j0 = c8 * 32;
        #pragma unroll 4
        for (int jj = 0; jj < 32; jj++) {
            int j = j0 + jj;
            float4 v4 = *(const float4*)(Ks + j * 68 + dg * 4);
            #pragma unroll
            for (int i = 0; i < 8; i++) {
                float p = S[(rg2 * 8 + i) * M + vt + j];
                acc[i].x = fmaf(p, v4.x, acc[i].x);
                acc[i].y = fmaf(p, v4.y, acc[i].y);
                acc[i].z = fmaf(p, v4.z, acc[i].z);
                acc[i].w = fmaf(p, v4.w, acc[i].w);
            }
        }
        __syncthreads();
    }

    // reduce the 8 c8-partials per (row, dg); reuse Qs as 256-float4 scratch
    if (outp) {
        float4* red = (float4*)Qs;
        #pragma unroll
        for (int i = 0; i < 8; i++) {
            __syncthreads();
            red[tid] = acc[i];
            __syncthreads();
            if (c8 < 4) {
                float4 o = red[tid + 128];
                acc[i].x += o.x; acc[i].y += o.y; acc[i].z += o.z; acc[i].w += o.w;
                red[tid] = acc[i];
            }
            __syncthreads();
            if (c8 < 2) {
                float4 o = red[tid + 64];
                acc[i].x += o.x; acc[i].y += o.y; acc[i].z += o.z; acc[i].w += o.w;
                red[tid] = acc[i];
            }
            __syncthreads();
            if (c8 == 0) {
                float4 o = red[tid + 32];
                acc[i].x += o.x; acc[i].y += o.y; acc[i].z += o.z; acc[i].w += o.w;
                int row = rg2 * 8 + i;
                ((float4*)outp)[(rowBase + m0 + row) * 16 + dg] = acc[i];
            }
        }
    }
}

// ---------------------------------------------------------------------------
// kernel_launch: derive dims from in_sizes, resolve output layout from
// out_size (reference returns (out, attn_weights): out first).
// ---------------------------------------------------------------------------
extern "C" void kernel_launch(void* const* d_in, const int* in_sizes, int n_in,
                              void* d_out, int out_size)
{
    const float* Q  = (const float*)d_in[0];
    const float* K  = (const float*)d_in[1];
    const float* V  = (const float*)d_in[2];
    const void* kpm = d_in[3];
    const void* am  = d_in[4];

    // attn_mask is (M, M); key_padding_mask is (N, M)
    int M = (int)(sqrt((double)in_sizes[4]) + 0.5);
    int N = in_sizes[3] / M;

    long long outElems  = (long long)N * M * 64;
    long long attnElems = (long long)N * M * M;

    float* outp  = (float*)d_out;
    float* attnp = 0;
    if ((long long)out_size == outElems + attnElems) {
        attnp = (float*)d_out + outElems;          // (out, attn_weights) packed
    } else if ((long long)out_size == attnElems) {
        outp = 0; attnp = (float*)d_out;           // attn only
    }                                              // else: out only

    size_t smem = (size_t)(BM * 68 + BK * 68 + (size_t)BM * M) * sizeof(float);
    cudaFuncSetAttribute(sdpa_kernel,
                         cudaFuncAttributeMaxDynamicSharedMemorySize, (int)smem);

    dim3 grid(M / BM, N);
    sdpa_kernel<<<grid, NTHREADS, smem>>>(Q, K, V, kpm, am, outp, attnp, N, M);
}